// round 5
// baseline (speedup 1.0000x reference)
#include <cuda_runtime.h>

// N = 2^26 FFT of real fp32 input -> stacked [2, N] (re, im) fp32.
// 3 global passes: N = 1024 * 1024 * 64.
//   P1: s=1     radix-1024 (16*16*4 in-block), real-input load, contiguous store
//   P2: s=1024  radix-1024, chunk-coalesced strided store
//   P3: s=2^20  radix-64 (4*16 in-block), twiddle-free, planar split-store

#define NFFT  (1u << 26)
#define NR    (NFFT >> 10)   // 65536: inner-sample stride for radix-1024 passes
#define NR64  (NFFT >> 6)    // 2^20:  inner-sample stride for radix-64 pass
#define TWO_PI 6.28318530717958647692f
#define INVN  (1.0f / 67108864.0f)

static __device__ float2 g_buf[NFFT];  // 512 MB scratch (sanctioned)

// exp(-2*pi*i*u/64), u = 0..15
__constant__ float2 c_w64[16] = {
    { 1.00000000000000000f, -0.00000000000000000f},
    { 0.99518472667219693f, -0.09801714032956060f},
    { 0.98078528040323044f, -0.19509032201612825f},
    { 0.95694033573220882f, -0.29028467725446233f},
    { 0.92387953251128676f, -0.38268343236508977f},
    { 0.88192126434835503f, -0.47139673682599764f},
    { 0.83146961230254524f, -0.55557023301960222f},
    { 0.77301045336273699f, -0.63439328416364549f},
    { 0.70710678118654752f, -0.70710678118654752f},
    { 0.63439328416364549f, -0.77301045336273699f},
    { 0.55557023301960222f, -0.83146961230254524f},
    { 0.47139673682599764f, -0.88192126434835503f},
    { 0.38268343236508977f, -0.92387953251128676f},
    { 0.29028467725446233f, -0.95694033573220882f},
    { 0.19509032201612825f, -0.98078528040323044f},
    { 0.09801714032956060f, -0.99518472667219693f}
};

__device__ __forceinline__ float2 cmul(float2 a, float2 b) {
    return make_float2(a.x * b.x - a.y * b.y, a.x * b.y + a.y * b.x);
}
__device__ __forceinline__ float2 cadd(float2 a, float2 b) {
    return make_float2(a.x + b.x, a.y + b.y);
}
__device__ __forceinline__ float2 csub(float2 a, float2 b) {
    return make_float2(a.x - b.x, a.y - b.y);
}
__device__ __forceinline__ float2 cmul_negi(float2 a) { return make_float2(a.y, -a.x); }
__device__ __forceinline__ float2 cmul_posi(float2 a) { return make_float2(-a.y, a.x); }

__device__ __forceinline__ void dft4(float2& x0, float2& x1, float2& x2, float2& x3) {
    float2 e = cadd(x0, x2), f = csub(x0, x2);
    float2 g = cadd(x1, x3), h = csub(x1, x3);
    x0 = cadd(e, g);
    x1 = cadd(f, cmul_negi(h));
    x2 = csub(e, g);
    x3 = cadd(f, cmul_posi(h));
}

// In-place forward DFT-16, natural order in/out (verified rounds 2-3).
__device__ __forceinline__ void dft16(float2 a[16]) {
    const float C1 = 0.92387953251128675613f;
    const float S1 = 0.38268343236508977173f;
    const float H  = 0.70710678118654752440f;
    const float2 W1 = make_float2( C1, -S1);
    const float2 W2 = make_float2(  H,  -H);
    const float2 W3 = make_float2( S1, -C1);
    const float2 W4 = make_float2(0.f, -1.f);
    const float2 W6 = make_float2( -H,  -H);
    const float2 W9 = make_float2(-C1,  S1);
    float2 b[16];
#pragma unroll
    for (int r1 = 0; r1 < 4; ++r1) {
        float2 x0 = a[r1], x1 = a[r1 + 4], x2 = a[r1 + 8], x3 = a[r1 + 12];
        float2 e = cadd(x0, x2), f = csub(x0, x2);
        float2 g = cadd(x1, x3), h = csub(x1, x3);
        b[r1 * 4 + 0] = cadd(e, g);
        b[r1 * 4 + 1] = cadd(f, cmul_negi(h));
        b[r1 * 4 + 2] = csub(e, g);
        b[r1 * 4 + 3] = cadd(f, cmul_posi(h));
    }
    b[5]  = cmul(b[5],  W1);
    b[6]  = cmul(b[6],  W2);
    b[7]  = cmul(b[7],  W3);
    b[9]  = cmul(b[9],  W2);
    b[10] = cmul(b[10], W4);
    b[11] = cmul(b[11], W6);
    b[13] = cmul(b[13], W3);
    b[14] = cmul(b[14], W6);
    b[15] = cmul(b[15], W9);
#pragma unroll
    for (int k1 = 0; k1 < 4; ++k1) {
        float2 x0 = b[k1], x1 = b[4 + k1], x2 = b[8 + k1], x3 = b[12 + k1];
        float2 e = cadd(x0, x2), f = csub(x0, x2);
        float2 g = cadd(x1, x3), h = csub(x1, x3);
        a[k1 + 0]  = cadd(e, g);
        a[k1 + 4]  = cadd(f, cmul_negi(h));
        a[k1 + 8]  = csub(e, g);
        a[k1 + 12] = cadd(f, cmul_posi(h));
    }
}

#define GS 1092u  // smem group stride (float2); GS % 16 == 4 => conflict-free
__device__ __forceinline__ unsigned fsw(unsigned m) { return m + (m >> 4); }

// ---------------------------------------------------------------------------
// Radix-1024 Stockham pass. Block = 256 threads, 4 consecutive groups.
// g = tid&3 (group), u = tid>>2 in [0,64). Inner 1024-FFT = 16 (s=1) *
// 16 (s=16) * 4 (s=256) with smem transposes. Outer twiddle w^k folded in.
// ---------------------------------------------------------------------------
template <bool REAL_IN, bool CONTIG_OUT>
__global__ void __launch_bounds__(256) fft1024_pass(const void* __restrict__ xin,
                                                    float2* __restrict__ y) {
    __shared__ float2 sm[4 * GS];
    const unsigned tid = threadIdx.x;
    const unsigned g = tid & 3u, u = tid >> 2;
    const unsigned t = blockIdx.x * 4u + g;
    const unsigned gb = g * GS;
    const float fu = (float)u;

    // ---- load: a[j] = x[t + (u + 64 j) * NR] ----
    float2 a[16];
    if (REAL_IN) {
        const float* x = (const float*)xin;
#pragma unroll
        for (int j = 0; j < 16; ++j)
            a[j] = make_float2(x[t + (u + 64u * (unsigned)j) * NR], 0.0f);
    } else {
        const float2* x = (const float2*)xin;
#pragma unroll
        for (int j = 0; j < 16; ++j)
            a[j] = x[t + (u + 64u * (unsigned)j) * NR];
    }

    // ---- SA: radix-16, s=1 within 1024. y1[16u+k] = DFT16 * w1024^{u k} ----
    dft16(a);
    {
        float sn, cs;
        __sincosf(-TWO_PI * fu * (1.0f / 1024.0f), &sn, &cs);
        float2 wa = make_float2(cs, sn), w = make_float2(1.f, 0.f);
#pragma unroll
        for (int k = 0; k < 16; ++k) {
            unsigned m = 16u * u + (unsigned)k;
            sm[gb + fsw(m)] = cmul(a[k], w);
            w = cmul(w, wa);
        }
    }
    __syncthreads();

    // ---- SB: radix-16, s=16. reads y1[u + 64 j]; writes y2[q+256p+16k]*w64^{p k}
#pragma unroll
    for (int j = 0; j < 16; ++j) {
        unsigned m = u + 64u * (unsigned)j;
        a[j] = sm[gb + fsw(m)];
    }
    dft16(a);
    __syncthreads();  // all SB reads complete before overwrite
    {
        unsigned q15 = u & 15u, p4 = u >> 4;
        float2 wb = c_w64[p4], w = make_float2(1.f, 0.f);
#pragma unroll
        for (int k = 0; k < 16; ++k) {
            unsigned m = q15 + 256u * p4 + 16u * (unsigned)k;
            sm[gb + fsw(m)] = cmul(a[k], w);
            w = cmul(w, wb);
        }
    }
    __syncthreads();

    // ---- SC: radix-4, s=256, twiddle-free. tt = u + 64 i ----
#pragma unroll
    for (int i = 0; i < 4; ++i) {
        float2 b0 = sm[gb + fsw(u + 64u * (unsigned)i)];
        float2 b1 = sm[gb + fsw(u + 64u * (unsigned)i + 256u)];
        float2 b2 = sm[gb + fsw(u + 64u * (unsigned)i + 512u)];
        float2 b3 = sm[gb + fsw(u + 64u * (unsigned)i + 768u)];
        dft4(b0, b1, b2, b3);
        a[4 * i + 0] = b0; a[4 * i + 1] = b1; a[4 * i + 2] = b2; a[4 * i + 3] = b3;
    }

    // ---- outer twiddle bases: w = e^{-2pi i ps / N}; need w^u, w^64, w^256 ----
    const unsigned q = CONTIG_OUT ? 0u : (t & 1023u);
    const unsigned ps = t - q;   // s=1: ps = t;  s=1024: ps = p*1024
    const float fps = (float)ps;
    float2 wu, w64b, w256b;
    { float sn, cs; __sincosf(-TWO_PI * (fps * fu) * INVN, &sn, &cs);     wu    = make_float2(cs, sn); }
    { float sn, cs; __sincosf(-TWO_PI * (fps * 64.0f) * INVN, &sn, &cs);  w64b  = make_float2(cs, sn); }
    { float sn, cs; __sincosf(-TWO_PI * (fps * 256.0f) * INVN, &sn, &cs); w256b = make_float2(cs, sn); }

    if (CONTIG_OUT) {
        __syncthreads();  // SC reads done before restage overwrite
        float2 wi = wu;
#pragma unroll
        for (int i = 0; i < 4; ++i) {
            float2 w = wi;
#pragma unroll
            for (int k3 = 0; k3 < 4; ++k3) {
                unsigned k = u + 64u * (unsigned)i + 256u * (unsigned)k3;
                sm[gb + fsw(k)] = cmul(a[4 * i + k3], w);
                w = cmul(w, w256b);
            }
            wi = cmul(wi, w64b);
        }
        __syncthreads();
        const unsigned base = blockIdx.x * 4096u;
#pragma unroll
        for (int it = 0; it < 16; ++it) {
            unsigned v = tid + 256u * (unsigned)it;
            unsigned gg = v >> 10, m = v & 1023u;
            y[base + v] = sm[gg * GS + fsw(m)];
        }
    } else {
        const unsigned base = q + (ps << 10);
        float2 wi = wu;
#pragma unroll
        for (int i = 0; i < 4; ++i) {
            float2 w = wi;
#pragma unroll
            for (int k3 = 0; k3 < 4; ++k3) {
                unsigned k = u + 64u * (unsigned)i + 256u * (unsigned)k3;
                y[base + (k << 10)] = cmul(a[4 * i + k3], w);
                w = cmul(w, w256b);
            }
            wi = cmul(wi, w64b);
        }
    }
}

// ---------------------------------------------------------------------------
// P3: radix-64 final pass (s = 2^20, twiddle-free), planar split store.
// Block = 256 threads, 16 consecutive groups: g = tid&15, u = tid>>4 in [0,16).
// Inner DFT-64 = radix-4 (s=1) then radix-16 (s=4, threads u<4).
// out[t + m*2^20] = X[m].
// ---------------------------------------------------------------------------
__global__ void __launch_bounds__(256) fft64_last(const float2* __restrict__ x,
                                                  float* __restrict__ out) {
    __shared__ float2 sm[16 * 65];
    const unsigned tid = threadIdx.x;
    const unsigned g = tid & 15u, u = tid >> 4;
    const unsigned t = blockIdx.x * 16u + g;
    const unsigned gb = g * 65u;

    // SA: radix-4, s=1: y1[4u+k] = DFT4_k(x[u + 16 j]) * w64^{u k}
    float2 b0 = x[t + (u +  0u) * NR64];
    float2 b1 = x[t + (u + 16u) * NR64];
    float2 b2 = x[t + (u + 32u) * NR64];
    float2 b3 = x[t + (u + 48u) * NR64];
    dft4(b0, b1, b2, b3);
    {
        float2 wsa = c_w64[u];
        sm[gb + 4u * u + 0u] = b0;
        sm[gb + 4u * u + 1u] = cmul(b1, wsa);
        float2 w2 = cmul(wsa, wsa);
        sm[gb + 4u * u + 2u] = cmul(b2, w2);
        sm[gb + 4u * u + 3u] = cmul(b3, cmul(w2, wsa));
    }
    __syncthreads();

    // SB: radix-16, s=4, twiddle-free (p=0): y2[q + 4k] = DFT16_k(y1[q + 4 j]),
    // q = u in [0,4). (Round-4 bug was here: read stride must be 4, not 16.)
    float2 c[16];
    if (u < 4u) {
#pragma unroll
        for (int j = 0; j < 16; ++j) c[j] = sm[gb + u + 4u * (unsigned)j];
        dft16(c);
    }
    __syncthreads();
    if (u < 4u) {
#pragma unroll
        for (int k = 0; k < 16; ++k) sm[gb + u + 4u * (unsigned)k] = c[k];
    }
    __syncthreads();

    // planar split store: re -> out[idx], im -> out[N + idx]
#pragma unroll
    for (int it = 0; it < 4; ++it) {
        unsigned m = 4u * u + (unsigned)it;
        float2 v = sm[gb + m];
        unsigned idx = t + m * NR64;
        out[idx] = v.x;
        out[NFFT + idx] = v.y;
    }
}

// ---------------------------------------------------------------------------
// Schedule: P1: x -> D (d_out as complex scratch); P2: D -> B; P3: B -> out.
// P3 never reads d_out, so the planar overwrite is hazard-free.
// ---------------------------------------------------------------------------
extern "C" void kernel_launch(void* const* d_in, const int* in_sizes, int n_in,
                              void* d_out, int out_size) {
    const float* x = (const float*)d_in[0];
    float* out = (float*)d_out;
    float2* D = (float2*)d_out;
    float2* B = nullptr;
    cudaGetSymbolAddress((void**)&B, g_buf);

    fft1024_pass<true,  true ><<<16384, 256>>>((const void*)x, D);
    fft1024_pass<false, false><<<16384, 256>>>((const void*)D, B);
    fft64_last<<<65536, 256>>>(B, out);
}

// round 6
// speedup vs baseline: 1.0861x; 1.0861x over previous
#include <cuda_runtime.h>

// N = 2^26 FFT of real fp32 input -> stacked [2, N] (re, im) fp32.
// 3 global passes: N = 1024 * 1024 * 64.
//   P1: s=1     radix-1024 (32x32 in registers, ONE smem transpose),
//               real-input load, contiguous restaged store
//   P2: s=1024  radix-1024, 128B-chunk coalesced strided store
//   P3: s=2^20  radix-64 (4*16 in-block), twiddle-free, planar split-store
// All warp-level global accesses are >=128B-chunked (16 consecutive groups).

#define NFFT  (1u << 26)
#define NR    (NFFT >> 10)   // 65536
#define NR64  (NFFT >> 6)    // 2^20
#define TWO_PI 6.28318530717958647692f
#define INVN  (1.0f / 67108864.0f)
#define GSTRIDE 1057u        // smem group stride (float2); 1057 % 16 == 1

static __device__ float2 g_buf[NFFT];  // 512 MB scratch (sanctioned)

// exp(-2*pi*i*k/32), k = 0..15
__constant__ float2 c_w32[16] = {
    { 1.00000000000000000f, -0.00000000000000000f},
    { 0.98078528040323045f, -0.19509032201612827f},
    { 0.92387953251128676f, -0.38268343236508977f},
    { 0.83146961230254524f, -0.55557023301960222f},
    { 0.70710678118654752f, -0.70710678118654752f},
    { 0.55557023301960222f, -0.83146961230254524f},
    { 0.38268343236508977f, -0.92387953251128676f},
    { 0.19509032201612827f, -0.98078528040323045f},
    { 0.00000000000000000f, -1.00000000000000000f},
    {-0.19509032201612827f, -0.98078528040323045f},
    {-0.38268343236508977f, -0.92387953251128676f},
    {-0.55557023301960222f, -0.83146961230254524f},
    {-0.70710678118654752f, -0.70710678118654752f},
    {-0.83146961230254524f, -0.55557023301960222f},
    {-0.92387953251128676f, -0.38268343236508977f},
    {-0.98078528040323045f, -0.19509032201612827f}
};

// exp(-2*pi*i*u/64), u = 0..15
__constant__ float2 c_w64[16] = {
    { 1.00000000000000000f, -0.00000000000000000f},
    { 0.99518472667219693f, -0.09801714032956060f},
    { 0.98078528040323044f, -0.19509032201612825f},
    { 0.95694033573220882f, -0.29028467725446233f},
    { 0.92387953251128676f, -0.38268343236508977f},
    { 0.88192126434835503f, -0.47139673682599764f},
    { 0.83146961230254524f, -0.55557023301960222f},
    { 0.77301045336273699f, -0.63439328416364549f},
    { 0.70710678118654752f, -0.70710678118654752f},
    { 0.63439328416364549f, -0.77301045336273699f},
    { 0.55557023301960222f, -0.83146961230254524f},
    { 0.47139673682599764f, -0.88192126434835503f},
    { 0.38268343236508977f, -0.92387953251128676f},
    { 0.29028467725446233f, -0.95694033573220882f},
    { 0.19509032201612825f, -0.98078528040323044f},
    { 0.09801714032956060f, -0.99518472667219693f}
};

__device__ __forceinline__ float2 cmul(float2 a, float2 b) {
    return make_float2(a.x * b.x - a.y * b.y, a.x * b.y + a.y * b.x);
}
__device__ __forceinline__ float2 cadd(float2 a, float2 b) {
    return make_float2(a.x + b.x, a.y + b.y);
}
__device__ __forceinline__ float2 csub(float2 a, float2 b) {
    return make_float2(a.x - b.x, a.y - b.y);
}
__device__ __forceinline__ float2 cmul_negi(float2 a) { return make_float2(a.y, -a.x); }
__device__ __forceinline__ float2 cmul_posi(float2 a) { return make_float2(-a.y, a.x); }

__device__ __forceinline__ void dft4(float2& x0, float2& x1, float2& x2, float2& x3) {
    float2 e = cadd(x0, x2), f = csub(x0, x2);
    float2 g = cadd(x1, x3), h = csub(x1, x3);
    x0 = cadd(e, g);
    x1 = cadd(f, cmul_negi(h));
    x2 = csub(e, g);
    x3 = cadd(f, cmul_posi(h));
}

// In-place forward DFT-16, natural order in/out (verified rounds 2-5).
__device__ __forceinline__ void dft16(float2 a[16]) {
    const float C1 = 0.92387953251128675613f;
    const float S1 = 0.38268343236508977173f;
    const float H  = 0.70710678118654752440f;
    const float2 W1 = make_float2( C1, -S1);
    const float2 W2 = make_float2(  H,  -H);
    const float2 W3 = make_float2( S1, -C1);
    const float2 W4 = make_float2(0.f, -1.f);
    const float2 W6 = make_float2( -H,  -H);
    const float2 W9 = make_float2(-C1,  S1);
    float2 b[16];
#pragma unroll
    for (int r1 = 0; r1 < 4; ++r1) {
        float2 x0 = a[r1], x1 = a[r1 + 4], x2 = a[r1 + 8], x3 = a[r1 + 12];
        float2 e = cadd(x0, x2), f = csub(x0, x2);
        float2 g = cadd(x1, x3), h = csub(x1, x3);
        b[r1 * 4 + 0] = cadd(e, g);
        b[r1 * 4 + 1] = cadd(f, cmul_negi(h));
        b[r1 * 4 + 2] = csub(e, g);
        b[r1 * 4 + 3] = cadd(f, cmul_posi(h));
    }
    b[5]  = cmul(b[5],  W1);
    b[6]  = cmul(b[6],  W2);
    b[7]  = cmul(b[7],  W3);
    b[9]  = cmul(b[9],  W2);
    b[10] = cmul(b[10], W4);
    b[11] = cmul(b[11], W6);
    b[13] = cmul(b[13], W3);
    b[14] = cmul(b[14], W6);
    b[15] = cmul(b[15], W9);
#pragma unroll
    for (int k1 = 0; k1 < 4; ++k1) {
        float2 x0 = b[k1], x1 = b[4 + k1], x2 = b[8 + k1], x3 = b[12 + k1];
        float2 e = cadd(x0, x2), f = csub(x0, x2);
        float2 g = cadd(x1, x3), h = csub(x1, x3);
        a[k1 + 0]  = cadd(e, g);
        a[k1 + 4]  = cadd(f, cmul_negi(h));
        a[k1 + 8]  = csub(e, g);
        a[k1 + 12] = cadd(f, cmul_posi(h));
    }
}

// In-place forward DFT-32, natural order in/out: even/odd split into two DFT-16.
__device__ __forceinline__ void dft32(float2 a[32]) {
    float2 E[16], O[16];
#pragma unroll
    for (int i = 0; i < 16; ++i) { E[i] = a[2 * i]; O[i] = a[2 * i + 1]; }
    dft16(E);
    dft16(O);
#pragma unroll
    for (int k = 0; k < 16; ++k) {
        float2 t = cmul(O[k], c_w32[k]);
        a[k]      = cadd(E[k], t);
        a[k + 16] = csub(E[k], t);
    }
}

// ---------------------------------------------------------------------------
// Radix-1024 Stockham pass. Block = 512 threads = 16 consecutive groups x
// 32 sub-threads. g = tid&15 (group), j2 = tid>>4 in [0,32).
// Inner 1024-point FFT = DFT32 (over j1, in regs) -> twiddle+transpose via
// smem -> DFT32 (over j2). Outer Stockham twiddle W^k folded into both layers.
// smem layout: group base g*GSTRIDE, element addr = lo + 33*hi (conflict-free
// per half-warp for all four access phases; GSTRIDE % 16 == 1).
// ---------------------------------------------------------------------------
template <bool REAL_IN, bool CONTIG_OUT>
__global__ void __launch_bounds__(512, 1) fft1024_pass(const void* __restrict__ xin,
                                                       float2* __restrict__ y) {
    extern __shared__ float2 sm[];
    const unsigned tid = threadIdx.x;
    const unsigned g = tid & 15u, j2 = tid >> 4;
    const unsigned t = blockIdx.x * 16u + g;
    const unsigned gb = g * GSTRIDE;

    // ---- load: a[j1] = x[t + (32*j1 + j2) * NR] (128B chunks per half-warp)
    float2 a[32];
    if (REAL_IN) {
        const float* x = (const float*)xin;
#pragma unroll
        for (int j1 = 0; j1 < 32; ++j1)
            a[j1] = make_float2(x[t + (32u * (unsigned)j1 + j2) * NR], 0.0f);
    } else {
        const float2* x = (const float2*)xin;
#pragma unroll
        for (int j1 = 0; j1 < 32; ++j1)
            a[j1] = x[t + (32u * (unsigned)j1 + j2) * NR];
    }

    // ---- layer 1: DFT32 over j1 -> k1; twiddle (w1024^{j2} * W)^{k1} ----
    dft32(a);

    const unsigned q = CONTIG_OUT ? 0u : (t & 1023u);
    const unsigned ps = t - q;
    const float fps = (float)ps;
    float2 W, W32, wj;
    { float sn, cs; __sincosf(-TWO_PI * fps * INVN, &sn, &cs);          W   = make_float2(cs, sn); }
    { float sn, cs; __sincosf(-TWO_PI * fps * 32.0f * INVN, &sn, &cs);  W32 = make_float2(cs, sn); }
    { float sn, cs; __sincosf(-TWO_PI * (float)j2 * (1.0f / 1024.0f), &sn, &cs); wj = make_float2(cs, sn); }
    const float2 v = cmul(wj, W);

    {
        float2 w = make_float2(1.f, 0.f);
#pragma unroll
        for (int k1 = 0; k1 < 32; ++k1) {
            sm[gb + j2 + 33u * (unsigned)k1] = cmul(a[k1], w);
            w = cmul(w, v);
        }
    }
    __syncthreads();

    // ---- transpose read + layer 2: DFT32 over j2 -> k2 ----
    const unsigned k1p = tid >> 4;
#pragma unroll
    for (int j = 0; j < 32; ++j)
        a[j] = sm[gb + (unsigned)j + 33u * k1p];
    dft32(a);

    if (CONTIG_OUT) {
        __syncthreads();  // layer-2 reads done before restage overwrite
        float2 w2 = make_float2(1.f, 0.f);
#pragma unroll
        for (int k2 = 0; k2 < 32; ++k2) {
            // k = k1p + 32*k2; skewed addr = k + (k>>5) = k1p + 33*k2
            sm[gb + k1p + 33u * (unsigned)k2] = cmul(a[k2], w2);
            w2 = cmul(w2, W32);
        }
        __syncthreads();
        const unsigned base = blockIdx.x * 16384u;
#pragma unroll
        for (int it = 0; it < 32; ++it) {
            unsigned vdx = tid + 512u * (unsigned)it;
            unsigned gg = vdx >> 10, m = vdx & 1023u;
            y[base + vdx] = sm[gg * GSTRIDE + m + (m >> 5)];
        }
    } else {
        const unsigned base = q + (ps << 10) + (k1p << 10);
        float2 w2 = make_float2(1.f, 0.f);
#pragma unroll
        for (int k2 = 0; k2 < 32; ++k2) {
            y[base + ((unsigned)k2 << 15)] = cmul(a[k2], w2);
            w2 = cmul(w2, W32);
        }
    }
}

// ---------------------------------------------------------------------------
// P3: radix-64 final pass (s = 2^20, twiddle-free), planar split store.
// Verified in round 5. Block = 256 threads, 16 consecutive groups.
// ---------------------------------------------------------------------------
__global__ void __launch_bounds__(256) fft64_last(const float2* __restrict__ x,
                                                  float* __restrict__ out) {
    __shared__ float2 sm[16 * 65];
    const unsigned tid = threadIdx.x;
    const unsigned g = tid & 15u, u = tid >> 4;
    const unsigned t = blockIdx.x * 16u + g;
    const unsigned gb = g * 65u;

    float2 b0 = x[t + (u +  0u) * NR64];
    float2 b1 = x[t + (u + 16u) * NR64];
    float2 b2 = x[t + (u + 32u) * NR64];
    float2 b3 = x[t + (u + 48u) * NR64];
    dft4(b0, b1, b2, b3);
    {
        float2 wsa = c_w64[u];
        sm[gb + 4u * u + 0u] = b0;
        sm[gb + 4u * u + 1u] = cmul(b1, wsa);
        float2 w2 = cmul(wsa, wsa);
        sm[gb + 4u * u + 2u] = cmul(b2, w2);
        sm[gb + 4u * u + 3u] = cmul(b3, cmul(w2, wsa));
    }
    __syncthreads();

    float2 c[16];
    if (u < 4u) {
#pragma unroll
        for (int j = 0; j < 16; ++j) c[j] = sm[gb + u + 4u * (unsigned)j];
        dft16(c);
    }
    __syncthreads();
    if (u < 4u) {
#pragma unroll
        for (int k = 0; k < 16; ++k) sm[gb + u + 4u * (unsigned)k] = c[k];
    }
    __syncthreads();

#pragma unroll
    for (int it = 0; it < 4; ++it) {
        unsigned m = 4u * u + (unsigned)it;
        float2 vv = sm[gb + m];
        unsigned idx = t + m * NR64;
        out[idx] = vv.x;
        out[NFFT + idx] = vv.y;
    }
}

// ---------------------------------------------------------------------------
// Schedule: P1: x -> D (d_out as complex scratch); P2: D -> B; P3: B -> out.
// ---------------------------------------------------------------------------
extern "C" void kernel_launch(void* const* d_in, const int* in_sizes, int n_in,
                              void* d_out, int out_size) {
    const float* x = (const float*)d_in[0];
    float* out = (float*)d_out;
    float2* D = (float2*)d_out;
    float2* B = nullptr;
    cudaGetSymbolAddress((void**)&B, g_buf);

    const size_t smem = (size_t)(16u * GSTRIDE) * sizeof(float2);  // 135,296 B
    cudaFuncSetAttribute(fft1024_pass<true,  true >,
                         cudaFuncAttributeMaxDynamicSharedMemorySize, (int)smem);
    cudaFuncSetAttribute(fft1024_pass<false, false>,
                         cudaFuncAttributeMaxDynamicSharedMemorySize, (int)smem);

    fft1024_pass<true,  true ><<<4096, 512, smem>>>((const void*)x, D);
    fft1024_pass<false, false><<<4096, 512, smem>>>((const void*)D, B);
    fft64_last<<<65536, 256>>>(B, out);
}

// round 7
// speedup vs baseline: 1.9826x; 1.8255x over previous
#include <cuda_runtime.h>

// N = 2^26 FFT of REAL fp32 input via half-length complex FFT:
//   z[n] = x[2n] + i x[2n+1]  (free: reinterpret input as float2, M = 2^25)
//   Z = FFT_M(z) in 3 passes (M = 256*256*512), then Hermitian unpack:
//   X[k] = A + W B,  X[M-k] = conj(A - W B),  X[N-k] = conj(X[k]),
//   A = (Z[k]+conj(Z[M-k]))/2, B = -i(Z[k]-conj(Z[M-k]))/2, W = e^{-2pi i k/N}.
// All kernels: 16 float2/thread, 16 consecutive groups/block (128B coalescing).

#define NFFT  (1u << 26)
#define MFFT  (1u << 25)
#define M256  (1u << 17)   // MFFT / 256
#define S512  (1u << 16)   // MFFT / 512
#define MHALF (1u << 24)
#define TWO_PI 6.28318530717958647692f
#define INVM  (1.0f / 33554432.0f)
#define INVN  (1.0f / 67108864.0f)

static __device__ float2 g_buf[NFFT];  // 512 MB scratch (sanctioned)

// exp(-2*pi*i*j/256), j = 0..15
__constant__ float2 c_w256[16] = {
    { 1.00000000000000000f, -0.00000000000000000f},
    { 0.99969881869620422f, -0.02454122852291229f},
    { 0.99879545620517241f, -0.04906767432741801f},
    { 0.99729045667869021f, -0.07356456359966743f},
    { 0.99518472667219693f, -0.09801714032956060f},
    { 0.99247953459870997f, -0.12241067519921620f},
    { 0.98917650996478101f, -0.14673047445536175f},
    { 0.98527764238894122f, -0.17096188876030122f},
    { 0.98078528040323044f, -0.19509032201612825f},
    { 0.97570213003852857f, -0.21910124015686980f},
    { 0.97003125319454397f, -0.24298017990326390f},
    { 0.96377606579543984f, -0.26671275747489837f},
    { 0.95694033573220882f, -0.29028467725446233f},
    { 0.94952818059303667f, -0.31368174039889152f},
    { 0.94154406518302081f, -0.33688985339222005f},
    { 0.93299279883473896f, -0.35989503653498817f}
};
// exp(-2*pi*i*k/32), k = 0..15
__constant__ float2 c_w32[16] = {
    { 1.00000000000000000f, -0.00000000000000000f},
    { 0.98078528040323045f, -0.19509032201612827f},
    { 0.92387953251128676f, -0.38268343236508977f},
    { 0.83146961230254524f, -0.55557023301960222f},
    { 0.70710678118654752f, -0.70710678118654752f},
    { 0.55557023301960222f, -0.83146961230254524f},
    { 0.38268343236508977f, -0.92387953251128676f},
    { 0.19509032201612827f, -0.98078528040323045f},
    { 0.00000000000000000f, -1.00000000000000000f},
    {-0.19509032201612827f, -0.98078528040323045f},
    {-0.38268343236508977f, -0.92387953251128676f},
    {-0.55557023301960222f, -0.83146961230254524f},
    {-0.70710678118654752f, -0.70710678118654752f},
    {-0.83146961230254524f, -0.55557023301960222f},
    {-0.92387953251128676f, -0.38268343236508977f},
    {-0.98078528040323045f, -0.19509032201612827f}
};

__device__ __forceinline__ float2 cmul(float2 a, float2 b) {
    return make_float2(a.x * b.x - a.y * b.y, a.x * b.y + a.y * b.x);
}
__device__ __forceinline__ float2 cadd(float2 a, float2 b) {
    return make_float2(a.x + b.x, a.y + b.y);
}
__device__ __forceinline__ float2 csub(float2 a, float2 b) {
    return make_float2(a.x - b.x, a.y - b.y);
}
__device__ __forceinline__ float2 cmul_negi(float2 a) { return make_float2(a.y, -a.x); }
__device__ __forceinline__ float2 cmul_posi(float2 a) { return make_float2(-a.y, a.x); }

// In-place forward DFT-16, natural order in/out (verified rounds 2-6).
__device__ __forceinline__ void dft16(float2 a[16]) {
    const float C1 = 0.92387953251128675613f;
    const float S1 = 0.38268343236508977173f;
    const float H  = 0.70710678118654752440f;
    const float2 W1 = make_float2( C1, -S1);
    const float2 W2 = make_float2(  H,  -H);
    const float2 W3 = make_float2( S1, -C1);
    const float2 W4 = make_float2(0.f, -1.f);
    const float2 W6 = make_float2( -H,  -H);
    const float2 W9 = make_float2(-C1,  S1);
    float2 b[16];
#pragma unroll
    for (int r1 = 0; r1 < 4; ++r1) {
        float2 x0 = a[r1], x1 = a[r1 + 4], x2 = a[r1 + 8], x3 = a[r1 + 12];
        float2 e = cadd(x0, x2), f = csub(x0, x2);
        float2 g = cadd(x1, x3), h = csub(x1, x3);
        b[r1 * 4 + 0] = cadd(e, g);
        b[r1 * 4 + 1] = cadd(f, cmul_negi(h));
        b[r1 * 4 + 2] = csub(e, g);
        b[r1 * 4 + 3] = cadd(f, cmul_posi(h));
    }
    b[5]  = cmul(b[5],  W1);
    b[6]  = cmul(b[6],  W2);
    b[7]  = cmul(b[7],  W3);
    b[9]  = cmul(b[9],  W2);
    b[10] = cmul(b[10], W4);
    b[11] = cmul(b[11], W6);
    b[13] = cmul(b[13], W3);
    b[14] = cmul(b[14], W6);
    b[15] = cmul(b[15], W9);
#pragma unroll
    for (int k1 = 0; k1 < 4; ++k1) {
        float2 x0 = b[k1], x1 = b[4 + k1], x2 = b[8 + k1], x3 = b[12 + k1];
        float2 e = cadd(x0, x2), f = csub(x0, x2);
        float2 g = cadd(x1, x3), h = csub(x1, x3);
        a[k1 + 0]  = cadd(e, g);
        a[k1 + 4]  = cadd(f, cmul_negi(h));
        a[k1 + 8]  = csub(e, g);
        a[k1 + 12] = cadd(f, cmul_posi(h));
    }
}

__device__ __forceinline__ unsigned swz(unsigned l) { return l + (l >> 8); }

// ---------------------------------------------------------------------------
// P1: radix-256, s=1, complex input (round-3 kernel, M-constants, cplx load).
// Block = 256 thr = 16 groups; output restaged -> contiguous 4096-elem store.
// ---------------------------------------------------------------------------
__global__ void __launch_bounds__(256) fft256_first(const float2* __restrict__ x,
                                                    float2* __restrict__ y) {
    __shared__ float2 sm[4112];
    unsigned tid = threadIdx.x;
    unsigned g = tid & 15u, j2 = tid >> 4;
    unsigned t = blockIdx.x * 16u + g;

    float2 a[16];
#pragma unroll
    for (int i = 0; i < 16; ++i) a[i] = x[t + (16u * (unsigned)i + j2) * M256];
    dft16(a);

    float sn, cs;
    __sincosf(-TWO_PI * (float)t * INVM, &sn, &cs);
    float2 wg = make_float2(cs, sn);
    float2 w1 = cmul(c_w256[j2], wg);
    float2 w = make_float2(1.f, 0.f);
#pragma unroll
    for (int k1 = 0; k1 < 16; ++k1) {
        sm[swz(tid + 256u * (unsigned)k1)] = cmul(a[k1], w);
        w = cmul(w, w1);
    }
    __syncthreads();

    unsigned k1p = tid >> 4;
#pragma unroll
    for (int j = 0; j < 16; ++j)
        a[j] = sm[swz(256u * k1p + 16u * (unsigned)j + g)];
    dft16(a);

    float2 w2 = cmul(wg, wg);
    w2 = cmul(w2, w2); w2 = cmul(w2, w2); w2 = cmul(w2, w2);  // wg^16
    float2 r[16];
    w = make_float2(1.f, 0.f);
#pragma unroll
    for (int k2 = 0; k2 < 16; ++k2) { r[k2] = cmul(a[k2], w); w = cmul(w, w2); }

    __syncthreads();
#pragma unroll
    for (int k2 = 0; k2 < 16; ++k2)
        sm[swz(256u * g + k1p + 16u * (unsigned)k2)] = r[k2];
    __syncthreads();

    unsigned base = blockIdx.x * 4096u;
#pragma unroll
    for (int i = 0; i < 16; ++i) {
        unsigned m = tid + 256u * (unsigned)i;
        y[base + m] = sm[swz(m)];
    }
}

// ---------------------------------------------------------------------------
// P2: radix-256 mid stage (round-3 kernel, M-constants). log2s = 8.
// ---------------------------------------------------------------------------
__global__ void __launch_bounds__(256) fft256_mid(const float2* __restrict__ x,
                                                  float2* __restrict__ y,
                                                  int log2s) {
    __shared__ float2 sm[4112];
    unsigned tid = threadIdx.x;
    unsigned g = tid & 15u, j2 = tid >> 4;
    unsigned t = blockIdx.x * 16u + g;
    unsigned s = 1u << log2s;
    unsigned q = t & (s - 1u);
    unsigned ps = t - q;

    float2 a[16];
#pragma unroll
    for (int i = 0; i < 16; ++i) a[i] = x[t + (16u * (unsigned)i + j2) * M256];
    dft16(a);

    float sn, cs;
    __sincosf(-TWO_PI * (float)ps * INVM, &sn, &cs);
    float2 wg = make_float2(cs, sn);
    float2 w1 = cmul(c_w256[j2], wg);
    float2 w = make_float2(1.f, 0.f);
#pragma unroll
    for (int k1 = 0; k1 < 16; ++k1) {
        sm[swz(tid + 256u * (unsigned)k1)] = cmul(a[k1], w);
        w = cmul(w, w1);
    }
    __syncthreads();

    unsigned k1p = tid >> 4;
#pragma unroll
    for (int j = 0; j < 16; ++j)
        a[j] = sm[swz(256u * k1p + 16u * (unsigned)j + g)];
    dft16(a);

    float2 w2 = cmul(wg, wg);
    w2 = cmul(w2, w2); w2 = cmul(w2, w2); w2 = cmul(w2, w2);
    unsigned base = q + (ps << 8) + (k1p << log2s);
    w = make_float2(1.f, 0.f);
#pragma unroll
    for (int k2 = 0; k2 < 16; ++k2) {
        y[base + ((unsigned)k2 << (log2s + 4))] = cmul(a[k2], w);
        w = cmul(w, w2);
    }
}

// ---------------------------------------------------------------------------
// P3: radix-512 final stage (s = 2^16, twiddle-free), natural-order output.
// Block = 512 thr = 16 groups x 32. 512 = 16(SA) * 16(SB) * 2(SC).
// smem: group stride 513 (odd => half-warp conflict-free; half-warp = same u).
// ---------------------------------------------------------------------------
#define GS3 513u
__global__ void __launch_bounds__(512) fft512_last(const float2* __restrict__ x,
                                                   float2* __restrict__ y) {
    extern __shared__ float2 sm[];
    const unsigned tid = threadIdx.x;
    const unsigned g = tid & 15u, u = tid >> 4;   // u in [0,32)
    const unsigned t = blockIdx.x * 16u + g;      // t in [0, 2^16)
    const unsigned gb = g * GS3;

    // load a[j] = x[t + (u + 32 j) * S512]
    float2 a[16];
#pragma unroll
    for (int j = 0; j < 16; ++j) a[j] = x[t + (u + 32u * (unsigned)j) * S512];

    // SA: radix-16, s=1: y1[16u + k] = DFT16_k * w512^{u k}
    dft16(a);
    {
        float sn, cs;
        __sincosf(-TWO_PI * (float)u * (1.0f / 512.0f), &sn, &cs);
        float2 wa = make_float2(cs, sn), w = make_float2(1.f, 0.f);
#pragma unroll
        for (int k = 0; k < 16; ++k) {
            sm[gb + 16u * u + (unsigned)k] = cmul(a[k], w);
            w = cmul(w, wa);
        }
    }
    __syncthreads();

    // SB: radix-16, s=16: reads y1[u + 32 j]; writes y2[q + 256 p + 16 k] * w32^{p k}
#pragma unroll
    for (int j = 0; j < 16; ++j) a[j] = sm[gb + u + 32u * (unsigned)j];
    dft16(a);
    __syncthreads();
    {
        unsigned q15 = u & 15u, p = u >> 4;  // p in {0,1}
#pragma unroll
        for (int k = 0; k < 16; ++k) {
            float2 v = (p == 0u) ? a[k] : cmul(a[k], c_w32[k]);
            sm[gb + q15 + 256u * p + 16u * (unsigned)k] = v;
        }
    }
    __syncthreads();

    // SC: radix-2, s=256, twiddle-free; store Z[t + k*S512], k natural order.
#pragma unroll
    for (int i = 0; i < 8; ++i) {
        unsigned t2 = u + 32u * (unsigned)i;
        float2 b0 = sm[gb + t2];
        float2 b1 = sm[gb + t2 + 256u];
        y[t + t2 * S512]           = cadd(b0, b1);
        y[t + (t2 + 256u) * S512]  = csub(b0, b1);
    }
}

// ---------------------------------------------------------------------------
// U: Hermitian unpack. Thread k in [0, M/2): P = A + W B, Q = A - W B;
//   X[k] = P, X[M-k] = conj(Q), X[N-k] = conj(P), X[M+k] = Q.
// k = 0 additionally writes the fixed points X[M/2] = conj(Z[M/2]),
// X[N-M/2] = Z[M/2], and skips the invalid N-k / M+k mirrors.
// ---------------------------------------------------------------------------
__global__ void __launch_bounds__(256) unpack(const float2* __restrict__ Z,
                                              float* __restrict__ out) {
    unsigned k = blockIdx.x * 256u + threadIdx.x;  // [0, 2^24)
    float2 Zk = Z[k];
    float2 Zm = Z[(MFFT - k) & (MFFT - 1u)];

    float2 A = make_float2(0.5f * (Zk.x + Zm.x), 0.5f * (Zk.y - Zm.y));
    float2 C = make_float2(0.5f * (Zk.x - Zm.x), 0.5f * (Zk.y + Zm.y));
    float2 B = make_float2(C.y, -C.x);

    float sn, cs;
    __sincosf(-TWO_PI * (float)k * INVN, &sn, &cs);
    float2 WB = cmul(make_float2(cs, sn), B);
    float2 P = cadd(A, WB);
    float2 Q = csub(A, WB);

    out[k] = P.x;            out[NFFT + k] = P.y;
    out[MFFT - k] = Q.x;     out[NFFT + MFFT - k] = -Q.y;
    if (k != 0u) {
        out[NFFT - k] = P.x;        out[2u * NFFT - k] = -P.y;
        out[MFFT + k] = Q.x;        out[NFFT + MFFT + k] = Q.y;
    } else {
        float2 Zh = Z[MHALF];
        out[MHALF] = Zh.x;                  out[NFFT + MHALF] = -Zh.y;
        out[NFFT - MHALF] = Zh.x;           out[NFFT + NFFT - MHALF] = Zh.y;
    }
}

// ---------------------------------------------------------------------------
// Schedule: P1: x(as float2) -> Blo; P2: Blo -> D (d_out scratch);
//           P3: D -> Bhi; U: Bhi -> out (planar d_out). No aliasing hazards.
// ---------------------------------------------------------------------------
extern "C" void kernel_launch(void* const* d_in, const int* in_sizes, int n_in,
                              void* d_out, int out_size) {
    const float2* z = (const float2*)d_in[0];   // N reals = M complex, free pack
    float* out = (float*)d_out;
    float2* D = (float2*)d_out;                 // scratch (M float2 fits)
    float2* Bbase = nullptr;
    cudaGetSymbolAddress((void**)&Bbase, g_buf);
    float2* Blo = Bbase;
    float2* Bhi = Bbase + MFFT;

    const size_t smem3 = (size_t)(16u * GS3) * sizeof(float2);  // 65,664 B
    cudaFuncSetAttribute(fft512_last,
                         cudaFuncAttributeMaxDynamicSharedMemorySize, (int)smem3);

    fft256_first<<<M256 / 16u, 256>>>(z, Blo);            // 8192 blocks
    fft256_mid  <<<M256 / 16u, 256>>>(Blo, D, 8);         // 8192 blocks
    fft512_last <<<S512 / 16u, 512, smem3>>>(D, Bhi);     // 4096 blocks
    unpack      <<<MHALF / 256u, 256>>>(Bhi, out);        // 65536 blocks
}

// round 8
// speedup vs baseline: 1.9867x; 1.0021x over previous
#include <cuda_runtime.h>

// N = 2^26 FFT of REAL fp32 input via half-length complex FFT (M = 2^25):
//   z[n] = x[2n] + i x[2n+1]  (free reinterpret), Z = FFT_M(z), then Hermitian
//   unpack X from Z. 3 kernels:
//   P1:  radix-256, s=1      z -> D      (d_out as complex scratch)
//   P2:  radix-256, s=256    D -> B      (g_buf)
//   P3U: radix-512 final (s=2^16) FUSED with Hermitian unpack: B -> planar out
// Recipe: 16 float2/thread, 16-consecutive-group coalescing (128B chunks).

#define NFFT  (1u << 26)
#define MFFT  (1u << 25)
#define M256  (1u << 17)   // MFFT / 256
#define S512  (1u << 16)   // MFFT / 512
#define TWO_PI 6.28318530717958647692f
#define INVM  (1.0f / 33554432.0f)
#define INVN  (1.0f / 67108864.0f)

static __device__ float2 g_buf[MFFT];  // 256 MB scratch (sanctioned)

// exp(-2*pi*i*j/256), j = 0..15
__constant__ float2 c_w256[16] = {
    { 1.00000000000000000f, -0.00000000000000000f},
    { 0.99969881869620422f, -0.02454122852291229f},
    { 0.99879545620517241f, -0.04906767432741801f},
    { 0.99729045667869021f, -0.07356456359966743f},
    { 0.99518472667219693f, -0.09801714032956060f},
    { 0.99247953459870997f, -0.12241067519921620f},
    { 0.98917650996478101f, -0.14673047445536175f},
    { 0.98527764238894122f, -0.17096188876030122f},
    { 0.98078528040323044f, -0.19509032201612825f},
    { 0.97570213003852857f, -0.21910124015686980f},
    { 0.97003125319454397f, -0.24298017990326390f},
    { 0.96377606579543984f, -0.26671275747489837f},
    { 0.95694033573220882f, -0.29028467725446233f},
    { 0.94952818059303667f, -0.31368174039889152f},
    { 0.94154406518302081f, -0.33688985339222005f},
    { 0.93299279883473896f, -0.35989503653498817f}
};
// exp(-2*pi*i*k/32), k = 0..15
__constant__ float2 c_w32[16] = {
    { 1.00000000000000000f, -0.00000000000000000f},
    { 0.98078528040323045f, -0.19509032201612827f},
    { 0.92387953251128676f, -0.38268343236508977f},
    { 0.83146961230254524f, -0.55557023301960222f},
    { 0.70710678118654752f, -0.70710678118654752f},
    { 0.55557023301960222f, -0.83146961230254524f},
    { 0.38268343236508977f, -0.92387953251128676f},
    { 0.19509032201612827f, -0.98078528040323045f},
    { 0.00000000000000000f, -1.00000000000000000f},
    {-0.19509032201612827f, -0.98078528040323045f},
    {-0.38268343236508977f, -0.92387953251128676f},
    {-0.55557023301960222f, -0.83146961230254524f},
    {-0.70710678118654752f, -0.70710678118654752f},
    {-0.83146961230254524f, -0.55557023301960222f},
    {-0.92387953251128676f, -0.38268343236508977f},
    {-0.98078528040323045f, -0.19509032201612827f}
};

__device__ __forceinline__ float2 cmul(float2 a, float2 b) {
    return make_float2(a.x * b.x - a.y * b.y, a.x * b.y + a.y * b.x);
}
__device__ __forceinline__ float2 cadd(float2 a, float2 b) {
    return make_float2(a.x + b.x, a.y + b.y);
}
__device__ __forceinline__ float2 csub(float2 a, float2 b) {
    return make_float2(a.x - b.x, a.y - b.y);
}
__device__ __forceinline__ float2 cmul_negi(float2 a) { return make_float2(a.y, -a.x); }
__device__ __forceinline__ float2 cmul_posi(float2 a) { return make_float2(-a.y, a.x); }

// In-place forward DFT-16, natural order in/out (verified rounds 2-7).
__device__ __forceinline__ void dft16(float2 a[16]) {
    const float C1 = 0.92387953251128675613f;
    const float S1 = 0.38268343236508977173f;
    const float H  = 0.70710678118654752440f;
    const float2 W1 = make_float2( C1, -S1);
    const float2 W2 = make_float2(  H,  -H);
    const float2 W3 = make_float2( S1, -C1);
    const float2 W4 = make_float2(0.f, -1.f);
    const float2 W6 = make_float2( -H,  -H);
    const float2 W9 = make_float2(-C1,  S1);
    float2 b[16];
#pragma unroll
    for (int r1 = 0; r1 < 4; ++r1) {
        float2 x0 = a[r1], x1 = a[r1 + 4], x2 = a[r1 + 8], x3 = a[r1 + 12];
        float2 e = cadd(x0, x2), f = csub(x0, x2);
        float2 g = cadd(x1, x3), h = csub(x1, x3);
        b[r1 * 4 + 0] = cadd(e, g);
        b[r1 * 4 + 1] = cadd(f, cmul_negi(h));
        b[r1 * 4 + 2] = csub(e, g);
        b[r1 * 4 + 3] = cadd(f, cmul_posi(h));
    }
    b[5]  = cmul(b[5],  W1);
    b[6]  = cmul(b[6],  W2);
    b[7]  = cmul(b[7],  W3);
    b[9]  = cmul(b[9],  W2);
    b[10] = cmul(b[10], W4);
    b[11] = cmul(b[11], W6);
    b[13] = cmul(b[13], W3);
    b[14] = cmul(b[14], W6);
    b[15] = cmul(b[15], W9);
#pragma unroll
    for (int k1 = 0; k1 < 4; ++k1) {
        float2 x0 = b[k1], x1 = b[4 + k1], x2 = b[8 + k1], x3 = b[12 + k1];
        float2 e = cadd(x0, x2), f = csub(x0, x2);
        float2 g = cadd(x1, x3), h = csub(x1, x3);
        a[k1 + 0]  = cadd(e, g);
        a[k1 + 4]  = cadd(f, cmul_negi(h));
        a[k1 + 8]  = csub(e, g);
        a[k1 + 12] = cadd(f, cmul_posi(h));
    }
}

__device__ __forceinline__ unsigned swz(unsigned l) { return l + (l >> 8); }

// ---------------------------------------------------------------------------
// P1: radix-256, s=1, complex input (verified round 7).
// ---------------------------------------------------------------------------
__global__ void __launch_bounds__(256) fft256_first(const float2* __restrict__ x,
                                                    float2* __restrict__ y) {
    __shared__ float2 sm[4112];
    unsigned tid = threadIdx.x;
    unsigned g = tid & 15u, j2 = tid >> 4;
    unsigned t = blockIdx.x * 16u + g;

    float2 a[16];
#pragma unroll
    for (int i = 0; i < 16; ++i) a[i] = x[t + (16u * (unsigned)i + j2) * M256];
    dft16(a);

    float sn, cs;
    __sincosf(-TWO_PI * (float)t * INVM, &sn, &cs);
    float2 wg = make_float2(cs, sn);
    float2 w1 = cmul(c_w256[j2], wg);
    float2 w = make_float2(1.f, 0.f);
#pragma unroll
    for (int k1 = 0; k1 < 16; ++k1) {
        sm[swz(tid + 256u * (unsigned)k1)] = cmul(a[k1], w);
        w = cmul(w, w1);
    }
    __syncthreads();

    unsigned k1p = tid >> 4;
#pragma unroll
    for (int j = 0; j < 16; ++j)
        a[j] = sm[swz(256u * k1p + 16u * (unsigned)j + g)];
    dft16(a);

    float2 w2 = cmul(wg, wg);
    w2 = cmul(w2, w2); w2 = cmul(w2, w2); w2 = cmul(w2, w2);  // wg^16
    float2 r[16];
    w = make_float2(1.f, 0.f);
#pragma unroll
    for (int k2 = 0; k2 < 16; ++k2) { r[k2] = cmul(a[k2], w); w = cmul(w, w2); }

    __syncthreads();
#pragma unroll
    for (int k2 = 0; k2 < 16; ++k2)
        sm[swz(256u * g + k1p + 16u * (unsigned)k2)] = r[k2];
    __syncthreads();

    unsigned base = blockIdx.x * 4096u;
#pragma unroll
    for (int i = 0; i < 16; ++i) {
        unsigned m = tid + 256u * (unsigned)i;
        y[base + m] = sm[swz(m)];
    }
}

// ---------------------------------------------------------------------------
// P2: radix-256 mid stage, log2s = 8 (verified round 7).
// ---------------------------------------------------------------------------
__global__ void __launch_bounds__(256) fft256_mid(const float2* __restrict__ x,
                                                  float2* __restrict__ y,
                                                  int log2s) {
    __shared__ float2 sm[4112];
    unsigned tid = threadIdx.x;
    unsigned g = tid & 15u, j2 = tid >> 4;
    unsigned t = blockIdx.x * 16u + g;
    unsigned s = 1u << log2s;
    unsigned q = t & (s - 1u);
    unsigned ps = t - q;

    float2 a[16];
#pragma unroll
    for (int i = 0; i < 16; ++i) a[i] = x[t + (16u * (unsigned)i + j2) * M256];
    dft16(a);

    float sn, cs;
    __sincosf(-TWO_PI * (float)ps * INVM, &sn, &cs);
    float2 wg = make_float2(cs, sn);
    float2 w1 = cmul(c_w256[j2], wg);
    float2 w = make_float2(1.f, 0.f);
#pragma unroll
    for (int k1 = 0; k1 < 16; ++k1) {
        sm[swz(tid + 256u * (unsigned)k1)] = cmul(a[k1], w);
        w = cmul(w, w1);
    }
    __syncthreads();

    unsigned k1p = tid >> 4;
#pragma unroll
    for (int j = 0; j < 16; ++j)
        a[j] = sm[swz(256u * k1p + 16u * (unsigned)j + g)];
    dft16(a);

    float2 w2 = cmul(wg, wg);
    w2 = cmul(w2, w2); w2 = cmul(w2, w2); w2 = cmul(w2, w2);
    unsigned base = q + (ps << 8) + (k1p << log2s);
    w = make_float2(1.f, 0.f);
#pragma unroll
    for (int k2 = 0; k2 < 16; ++k2) {
        y[base + ((unsigned)k2 << (log2s + 4))] = cmul(a[k2], w);
        w = cmul(w, w2);
    }
}

// ---------------------------------------------------------------------------
// P3U: radix-512 final stage (s = 2^16, twiddle-free) FUSED with Hermitian
// unpack. Block = 1024 threads = 32 groups: chunk A (t = 16b+g) + chunk B
// (mirror t = (S512-16b-15+g) mod S512). FFT phase identical to the verified
// fft512_last, but Z stays in smem. Unpack: for each m = t + k*S512, t in A:
//   A = (Z[m]+conj Z[M-m])/2, B = -i(Z[m]-conj Z[M-m])/2, W = e^{-2pi i m/N}
//   P = A + W B -> X[m];  conj P -> X[N-m];  Q = A - W B -> X[M+m];
//   conj Q -> X[M-m].  Grid = 2049 (last block covers the self-mirror chunk;
//   overlap writes are bitwise-identical, benign).
// smem: 32 groups, stride GSK = 513 (odd, ==1 mod 16: conflict-free both for
// within-group phases and the cross-group stride-GSK unpack reads).
// ---------------------------------------------------------------------------
#define GSK 513u
__global__ void __launch_bounds__(1024, 1) fft512_unpack(const float2* __restrict__ x,
                                                         float* __restrict__ out) {
    extern __shared__ float2 sm[];
    const unsigned tid = threadIdx.x;
    const unsigned bb = blockIdx.x;

    // ======================= FFT phase (32 groups) =======================
    {
        const unsigned g = tid & 15u;
        const unsigned u = (tid >> 4) & 31u;
        const unsigned half = tid >> 9;
        const unsigned tA = 16u * bb + g;
        const unsigned tB = (S512 - 16u * bb - 15u + g) & (S512 - 1u);
        const unsigned t = half ? tB : tA;
        const unsigned gb = (half * 16u + g) * GSK;

        float2 a[16];
#pragma unroll
        for (int j = 0; j < 16; ++j) a[j] = x[t + (u + 32u * (unsigned)j) * S512];

        // SA: radix-16, s=1
        dft16(a);
        {
            float sn, cs;
            __sincosf(-TWO_PI * (float)u * (1.0f / 512.0f), &sn, &cs);
            float2 wa = make_float2(cs, sn), w = make_float2(1.f, 0.f);
#pragma unroll
            for (int k = 0; k < 16; ++k) {
                sm[gb + 16u * u + (unsigned)k] = cmul(a[k], w);
                w = cmul(w, wa);
            }
        }
        __syncthreads();

        // SB: radix-16, s=16
#pragma unroll
        for (int j = 0; j < 16; ++j) a[j] = sm[gb + u + 32u * (unsigned)j];
        dft16(a);
        __syncthreads();
        {
            unsigned q15 = u & 15u, p = u >> 4;
#pragma unroll
            for (int k = 0; k < 16; ++k) {
                float2 v = (p == 0u) ? a[k] : cmul(a[k], c_w32[k]);
                sm[gb + q15 + 256u * p + 16u * (unsigned)k] = v;
            }
        }
        __syncthreads();

        // SC: radix-2, s=256, in-place in smem (same-thread read+write)
#pragma unroll
        for (int i = 0; i < 8; ++i) {
            unsigned t2 = u + 32u * (unsigned)i;
            float2 b0 = sm[gb + t2];
            float2 b1 = sm[gb + t2 + 256u];
            sm[gb + t2]        = cadd(b0, b1);
            sm[gb + t2 + 256u] = csub(b0, b1);
        }
    }
    __syncthreads();

    // ======================= unpack phase =======================
    {
        const unsigned gA = tid & 15u;
        const unsigned uu = tid >> 4;          // [0, 64)
        const unsigned t = 16u * bb + gA;      // A-group t (< S512)
        const unsigned gbA = gA * GSK;
        const unsigned gbB = (31u - gA) * GSK; // mirror group (B half)
        const bool tzero = (t == 0u);

        float m0f = (float)(t + uu * S512);
        float sn, cs;
        __sincosf(-TWO_PI * m0f * INVN, &sn, &cs);
        float2 W = make_float2(cs, sn);
        const float2 Winc = c_w32[2];          // e^{-2pi i/16}: k += 64 step

#pragma unroll
        for (int j = 0; j < 8; ++j) {
            unsigned k = uu + 64u * (unsigned)j;
            float2 Zk = sm[gbA + k];
            unsigned kp = tzero ? ((512u - k) & 511u) : (511u - k);
            float2 Zm = sm[gbB + kp];

            float2 A = make_float2(0.5f * (Zk.x + Zm.x), 0.5f * (Zk.y - Zm.y));
            float2 C = make_float2(0.5f * (Zk.x - Zm.x), 0.5f * (Zk.y + Zm.y));
            float2 B = make_float2(C.y, -C.x);
            float2 WB = cmul(W, B);
            float2 P = cadd(A, WB);
            float2 Q = csub(A, WB);

            unsigned m = t + k * S512;               // [0, M)
            unsigned i3 = (NFFT - m) & (NFFT - 1u);  // N - m (mod N)
            unsigned i2 = MFFT - m;
            unsigned i4 = MFFT + m;

            out[m]  = P.x;   out[NFFT + m]  = P.y;
            out[i3] = P.x;   out[NFFT + i3] = -P.y;
            out[i2] = Q.x;   out[NFFT + i2] = -Q.y;
            out[i4] = Q.x;   out[NFFT + i4] = Q.y;

            W = cmul(W, Winc);
        }
    }
}

// ---------------------------------------------------------------------------
// Schedule: P1: z -> D (d_out scratch); P2: D -> B (g_buf); P3U: B -> out.
// P3U reads only g_buf, writes only d_out: no aliasing hazard.
// ---------------------------------------------------------------------------
extern "C" void kernel_launch(void* const* d_in, const int* in_sizes, int n_in,
                              void* d_out, int out_size) {
    const float2* z = (const float2*)d_in[0];   // N reals = M complex (free pack)
    float* out = (float*)d_out;
    float2* D = (float2*)d_out;                 // M float2 scratch fits in out
    float2* B = nullptr;
    cudaGetSymbolAddress((void**)&B, g_buf);

    const size_t smem3 = (size_t)(32u * GSK) * sizeof(float2);  // 131,328 B
    cudaFuncSetAttribute(fft512_unpack,
                         cudaFuncAttributeMaxDynamicSharedMemorySize, (int)smem3);

    fft256_first <<<M256 / 16u, 256>>>(z, D);          // 8192 blocks
    fft256_mid   <<<M256 / 16u, 256>>>(D, B, 8);       // 8192 blocks
    fft512_unpack<<<S512 / 32u + 1u, 1024, smem3>>>(B, out);  // 2049 blocks
}